// round 7
// baseline (speedup 1.0000x reference)
#include <cuda_runtime.h>
#include <math.h>

// Problem constants
#define SQ    2048
#define SKV   2048
#define DM    512
#define NH    8
#define DHEAD 64

// ---------------------------------------------------------------------------
// Scratch (device globals: allocation-guard safe)
// ---------------------------------------------------------------------------
__device__ float g_q[NH * SQ * DHEAD];        // [h][s][d]
__device__ float g_k[NH * SKV * DHEAD];       // [h][t][d]
__device__ float g_v[NH * SKV * DHEAD];       // [h][t][d]
__device__ float g_concat[SQ * DM];           // [s][h*64 + c]

// ---------------------------------------------------------------------------
// Fused Q/K/V projection GEMMs.
// grid = (SQ/64, NH, 3); block = 256.
// out[h, s, c] = X[s, :] @ W[h, :, c] + b[h, c]
// 64x64 output tile per block, BK=32, 4x4 register micro-tile.
// ---------------------------------------------------------------------------
__global__ __launch_bounds__(256) void proj_qkv_kernel(
    const float* __restrict__ X0, const float* __restrict__ W0, const float* __restrict__ b0,
    const float* __restrict__ X1, const float* __restrict__ W1, const float* __restrict__ b1,
    const float* __restrict__ X2, const float* __restrict__ W2, const float* __restrict__ b2)
{
    __shared__ float As[32][64];   // As[kk][r]  (X tile, transposed)
    __shared__ float Bs[32][64];   // Bs[kk][c]  (W tile, natural)

    const float* X; const float* W; const float* b; float* out;
    if (blockIdx.z == 0)      { X = X0; W = W0; b = b0; out = g_q; }
    else if (blockIdx.z == 1) { X = X1; W = W1; b = b1; out = g_k; }
    else                      { X = X2; W = W2; b = b2; out = g_v; }

    const int h  = blockIdx.y;
    const int s0 = blockIdx.x * 64;
    const float* Wh = W + (size_t)h * DM * DHEAD;

    const int tid = threadIdx.x;
    const int ty  = tid >> 4;    // 0..15 -> output rows ty*4..ty*4+3
    const int tx  = tid & 15;    // 0..15 -> output cols tx*4..tx*4+3

    float acc[4][4];
    #pragma unroll
    for (int i = 0; i < 4; i++)
        #pragma unroll
        for (int j = 0; j < 4; j++) acc[i][j] = 0.f;

    for (int kb = 0; kb < DM; kb += 32) {
        // Load X tile transposed: As[kk][r] = X[s0+r][kb+kk]
        // mapping: lanes take consecutive r (conflict-free STS), same d-group
        #pragma unroll
        for (int t = tid; t < 512; t += 256) {
            int r  = t & 63;
            int k4 = (t >> 6) << 2;     // 0..28
            float4 v = *(const float4*)(X + (size_t)(s0 + r) * DM + kb + k4);
            As[k4 + 0][r] = v.x; As[k4 + 1][r] = v.y;
            As[k4 + 2][r] = v.z; As[k4 + 3][r] = v.w;
        }
        // Load W tile natural: Bs[kk][c] = W[h][kb+kk][c]
        #pragma unroll
        for (int t = tid; t < 512; t += 256) {
            int kk = t >> 4;
            int c4 = (t & 15) << 2;
            *(float4*)&Bs[kk][c4] = *(const float4*)(Wh + (size_t)(kb + kk) * DHEAD + c4);
        }
        __syncthreads();

        #pragma unroll
        for (int kk = 0; kk < 32; kk++) {
            float4 a  = *(const float4*)&As[kk][ty << 2];   // uniform kk -> broadcast
            float4 bb = *(const float4*)&Bs[kk][tx << 2];   // uniform kk -> contiguous
            float av[4] = {a.x, a.y, a.z, a.w};
            float bv[4] = {bb.x, bb.y, bb.z, bb.w};
            #pragma unroll
            for (int i = 0; i < 4; i++)
                #pragma unroll
                for (int j = 0; j < 4; j++)
                    acc[i][j] += av[i] * bv[j];
        }
        __syncthreads();
    }

    float4 bias = *(const float4*)(b + h * DHEAD + (tx << 2));
    #pragma unroll
    for (int i = 0; i < 4; i++) {
        int s = s0 + (ty << 2) + i;
        float4 o;
        o.x = acc[i][0] + bias.x;
        o.y = acc[i][1] + bias.y;
        o.z = acc[i][2] + bias.z;
        o.w = acc[i][3] + bias.w;
        *(float4*)(out + ((size_t)h * SKV + s) * DHEAD + (tx << 2)) = o;
    }
}

// ---------------------------------------------------------------------------
// Fused flash attention per (head, 64-query block).
// grid = (SQ/64, NH); block = 256 (16x16 threads, 4x4 micro-tiles).
// Online softmax; writes normalized output directly into g_concat.
// smem = 3 * 16 KB = 48 KB exactly (KtP is K-tile then reused as P).
// ---------------------------------------------------------------------------
__global__ __launch_bounds__(256) void attn_kernel()
{
    __shared__ float Qt [64][64];   // Qt[d][r]
    __shared__ float KtP[64][64];   // Kt[d][j], reused as Ps[r][j]
    __shared__ float Vs [64][64];   // Vs[j][c]

    const int h   = blockIdx.y;
    const int s0  = blockIdx.x * 64;
    const int tid = threadIdx.x;
    const int ty  = tid >> 4;       // query rows ty*4..+3
    const int tx  = tid & 15;       // kv cols / out cols tx*4..+3

    const float* Qh = g_q + ((size_t)h * SQ + s0) * DHEAD;

    // Load Q tile transposed (once)
    #pragma unroll
    for (int t = tid; t < 1024; t += 256) {
        int r  = t & 63;
        int d4 = (t >> 6) << 2;
        float4 v = *(const float4*)(Qh + r * DHEAD + d4);
        Qt[d4 + 0][r] = v.x; Qt[d4 + 1][r] = v.y;
        Qt[d4 + 2][r] = v.z; Qt[d4 + 3][r] = v.w;
    }

    float m_i[4], l_i[4], O[4][4];
    #pragma unroll
    for (int i = 0; i < 4; i++) {
        m_i[i] = -3.0e38f;
        l_i[i] = 0.f;
        #pragma unroll
        for (int j = 0; j < 4; j++) O[i][j] = 0.f;
    }
    const float scale = 0.125f;   // 1/sqrt(64)

    for (int t0 = 0; t0 < SKV; t0 += 64) {
        const float* Kh = g_k + ((size_t)h * SKV + t0) * DHEAD;
        const float* Vh = g_v + ((size_t)h * SKV + t0) * DHEAD;

        __syncthreads();  // prior iter's reads of KtP/Vs done (also fences Qt on iter 0)

        // K tile transposed: KtP[d][j] = K[t0+j][d]
        #pragma unroll
        for (int t = tid; t < 1024; t += 256) {
            int j  = t & 63;
            int d4 = (t >> 6) << 2;
            float4 v = *(const float4*)(Kh + j * DHEAD + d4);
            KtP[d4 + 0][j] = v.x; KtP[d4 + 1][j] = v.y;
            KtP[d4 + 2][j] = v.z; KtP[d4 + 3][j] = v.w;
        }
        // V tile natural: Vs[j][c] = V[t0+j][c]
        #pragma unroll
        for (int t = tid; t < 1024; t += 256) {
            int j  = t >> 4;
            int c4 = (t & 15) << 2;
            *(float4*)&Vs[j][c4] = *(const float4*)(Vh + j * DHEAD + c4);
        }
        __syncthreads();

        // ---- scores s[i][j] = scale * Q[r_i] . K[j_j] ----
        float s[4][4];
        #pragma unroll
        for (int i = 0; i < 4; i++)
            #pragma unroll
            for (int j = 0; j < 4; j++) s[i][j] = 0.f;

        #pragma unroll 16
        for (int d = 0; d < 64; d++) {
            float4 a  = *(const float4*)&Qt [d][ty << 2];
            float4 bb = *(const float4*)&KtP[d][tx << 2];
            float av[4] = {a.x, a.y, a.z, a.w};
            float bv[4] = {bb.x, bb.y, bb.z, bb.w};
            #pragma unroll
            for (int i = 0; i < 4; i++)
                #pragma unroll
                for (int j = 0; j < 4; j++)
                    s[i][j] += av[i] * bv[j];
        }

        // ---- online softmax update (row state reduced across the 16 tx lanes) ----
        #pragma unroll
        for (int i = 0; i < 4; i++) {
            #pragma unroll
            for (int j = 0; j < 4; j++) s[i][j] *= scale;

            float mx = fmaxf(fmaxf(s[i][0], s[i][1]), fmaxf(s[i][2], s[i][3]));
            mx = fmaxf(mx, __shfl_xor_sync(0xffffffffu, mx, 1));
            mx = fmaxf(mx, __shfl_xor_sync(0xffffffffu, mx, 2));
            mx = fmaxf(mx, __shfl_xor_sync(0xffffffffu, mx, 4));
            mx = fmaxf(mx, __shfl_xor_sync(0xffffffffu, mx, 8));

            float m_new = fmaxf(m_i[i], mx);
            float alpha = __expf(m_i[i] - m_new);

            float rs = 0.f;
            #pragma unroll
            for (int j = 0; j < 4; j++) {
                float p = __expf(s[i][j] - m_new);
                s[i][j] = p;
                rs += p;
            }
            rs += __shfl_xor_sync(0xffffffffu, rs, 1);
            rs += __shfl_xor_sync(0xffffffffu, rs, 2);
            rs += __shfl_xor_sync(0xffffffffu, rs, 4);
            rs += __shfl_xor_sync(0xffffffffu, rs, 8);

            l_i[i] = l_i[i] * alpha + rs;
            m_i[i] = m_new;
            #pragma unroll
            for (int j = 0; j < 4; j++) O[i][j] *= alpha;
        }

        __syncthreads();  // all threads done reading KtP as K-tile

        // Write P into KtP (natural layout Ps[r][j])
        #pragma unroll
        for (int i = 0; i < 4; i++)
            *(float4*)&KtP[(ty << 2) + i][tx << 2] =
                make_float4(s[i][0], s[i][1], s[i][2], s[i][3]);
        __syncthreads();

        // ---- O[i][c] += sum_j P[r_i][j] * V[j][c] ----
        #pragma unroll 16
        for (int j = 0; j < 64; j++) {
            float4 bv = *(const float4*)&Vs[j][tx << 2];
            float a0 = KtP[(ty << 2) + 0][j];
            float a1 = KtP[(ty << 2) + 1][j];
            float a2 = KtP[(ty << 2) + 2][j];
            float a3 = KtP[(ty << 2) + 3][j];
            O[0][0] += a0 * bv.x; O[0][1] += a0 * bv.y; O[0][2] += a0 * bv.z; O[0][3] += a0 * bv.w;
            O[1][0] += a1 * bv.x; O[1][1] += a1 * bv.y; O[1][2] += a1 * bv.z; O[1][3] += a1 * bv.w;
            O[2][0] += a2 * bv.x; O[2][1] += a2 * bv.y; O[2][2] += a2 * bv.z; O[2][3] += a2 * bv.w;
            O[3][0] += a3 * bv.x; O[3][1] += a3 * bv.y; O[3][2] += a3 * bv.z; O[3][3] += a3 * bv.w;
        }
    }

    // Normalize and write into concat layout [s][h*64 + c]
    #pragma unroll
    for (int i = 0; i < 4; i++) {
        float inv = 1.0f / l_i[i];
        float4 o = make_float4(O[i][0] * inv, O[i][1] * inv, O[i][2] * inv, O[i][3] * inv);
        *(float4*)(g_concat + (size_t)(s0 + (ty << 2) + i) * DM + h * DHEAD + (tx << 2)) = o;
    }
}

// ---------------------------------------------------------------------------
// Output projection: out = concat @ Wo + bo.   Wo: [512, 512] row-major.
// grid = (SQ/64, DM/64); block = 256.
// ---------------------------------------------------------------------------
__global__ __launch_bounds__(256) void out_proj_kernel(
    const float* __restrict__ Wo,
    const float* __restrict__ bo,
    float* __restrict__ out)
{
    __shared__ float As[32][64];   // As[kk][r]
    __shared__ float Bs[32][64];   // Bs[kk][c]

    const int s0 = blockIdx.x * 64;
    const int n0 = blockIdx.y * 64;
    const int tid = threadIdx.x;
    const int ty  = tid >> 4;
    const int tx  = tid & 15;

    float acc[4][4];
    #pragma unroll
    for (int i = 0; i < 4; i++)
        #pragma unroll
        for (int j = 0; j < 4; j++) acc[i][j] = 0.f;

    for (int kb = 0; kb < DM; kb += 32) {
        #pragma unroll
        for (int t = tid; t < 512; t += 256) {
            int r  = t & 63;
            int k4 = (t >> 6) << 2;
            float4 v = *(const float4*)(g_concat + (size_t)(s0 + r) * DM + kb + k4);
            As[k4 + 0][r] = v.x; As[k4 + 1][r] = v.y;
            As[k4 + 2][r] = v.z; As[k4 + 3][r] = v.w;
        }
        #pragma unroll
        for (int t = tid; t < 512; t += 256) {
            int kk = t >> 4;
            int c4 = (t & 15) << 2;
            *(float4*)&Bs[kk][c4] = *(const float4*)(Wo + (size_t)(kb + kk) * DM + n0 + c4);
        }
        __syncthreads();

        #pragma unroll
        for (int kk = 0; kk < 32; kk++) {
            float4 a  = *(const float4*)&As[kk][ty << 2];
            float4 bb = *(const float4*)&Bs[kk][tx << 2];
            float av[4] = {a.x, a.y, a.z, a.w};
            float bv[4] = {bb.x, bb.y, bb.z, bb.w};
            #pragma unroll
            for (int i = 0; i < 4; i++)
                #pragma unroll
                for (int j = 0; j < 4; j++)
                    acc[i][j] += av[i] * bv[j];
        }
        __syncthreads();
    }

    float4 bias = *(const float4*)(bo + n0 + (tx << 2));
    #pragma unroll
    for (int i = 0; i < 4; i++) {
        int s = s0 + (ty << 2) + i;
        float4 o;
        o.x = acc[i][0] + bias.x;
        o.y = acc[i][1] + bias.y;
        o.z = acc[i][2] + bias.z;
        o.w = acc[i][3] + bias.w;
        *(float4*)(out + (size_t)s * DM + n0 + (tx << 2)) = o;
    }
}

// ---------------------------------------------------------------------------
// Launch
// ---------------------------------------------------------------------------
extern "C" void kernel_launch(void* const* d_in, const int* in_sizes, int n_in,
                              void* d_out, int out_size)
{
    const float* emb = (const float*)d_in[0];
    const float* K   = (const float*)d_in[1];
    const float* V   = (const float*)d_in[2];
    const float* Wq  = (const float*)d_in[3];
    const float* bq  = (const float*)d_in[4];
    const float* Wk  = (const float*)d_in[5];
    const float* bk  = (const float*)d_in[6];
    const float* Wv  = (const float*)d_in[7];
    const float* bv  = (const float*)d_in[8];
    const float* Wo  = (const float*)d_in[9];
    const float* bo  = (const float*)d_in[10];
    float* out = (float*)d_out;

    dim3 blk(256);

    // Q/K/V projections in one launch (z selects which projection)
    proj_qkv_kernel<<<dim3(SQ / 64, NH, 3), blk>>>(
        emb, Wq, bq,
        K,   Wk, bk,
        V,   Wv, bv);

    // Fused flash attention -> g_concat
    attn_kernel<<<dim3(SQ / 64, NH), blk>>>();

    // Final output projection
    out_proj_kernel<<<dim3(SQ / 64, DM / 64), blk>>>(Wo, bo, out);
}

// round 9
// speedup vs baseline: 1.0006x; 1.0006x over previous
#include <cuda_runtime.h>
#include <math.h>

// Problem constants
#define SQ    2048
#define SKV   2048
#define DM    512
#define NH    8
#define DHEAD 64

// ---------------------------------------------------------------------------
// Scratch (device globals: allocation-guard safe)
// ---------------------------------------------------------------------------
__device__ float g_q[NH * SQ * DHEAD];        // [h][s][d]
__device__ float g_k[NH * SKV * DHEAD];       // [h][t][d]
__device__ float g_v[NH * SKV * DHEAD];       // [h][t][d]
__device__ float g_concat[SQ * DM];           // [s][h*64 + c]

// ---------------------------------------------------------------------------
// Fused Q/K/V projection GEMMs.
// grid = (SQ/64, NH, 3); block = 256.
// out[h, s, c] = X[s, :] @ W[h, :, c] + b[h, c]
// 64x64 output tile per block, BK=32, 4x4 register micro-tile.
// ---------------------------------------------------------------------------
__global__ __launch_bounds__(256) void proj_qkv_kernel(
    const float* __restrict__ X0, const float* __restrict__ W0, const float* __restrict__ b0,
    const float* __restrict__ X1, const float* __restrict__ W1, const float* __restrict__ b1,
    const float* __restrict__ X2, const float* __restrict__ W2, const float* __restrict__ b2)
{
    __shared__ float As[32][64];   // As[kk][r]  (X tile, transposed)
    __shared__ float Bs[32][64];   // Bs[kk][c]  (W tile, natural)

    const float* X; const float* W; const float* b; float* out;
    if (blockIdx.z == 0)      { X = X0; W = W0; b = b0; out = g_q; }
    else if (blockIdx.z == 1) { X = X1; W = W1; b = b1; out = g_k; }
    else                      { X = X2; W = W2; b = b2; out = g_v; }

    const int h  = blockIdx.y;
    const int s0 = blockIdx.x * 64;
    const float* Wh = W + (size_t)h * DM * DHEAD;

    const int tid = threadIdx.x;
    const int ty  = tid >> 4;    // 0..15 -> output rows ty*4..ty*4+3
    const int tx  = tid & 15;    // 0..15 -> output cols tx*4..tx*4+3

    float acc[4][4];
    #pragma unroll
    for (int i = 0; i < 4; i++)
        #pragma unroll
        for (int j = 0; j < 4; j++) acc[i][j] = 0.f;

    for (int kb = 0; kb < DM; kb += 32) {
        // Load X tile transposed: As[kk][r] = X[s0+r][kb+kk]
        // mapping: lanes take consecutive r (conflict-free STS), same d-group
        #pragma unroll
        for (int t = tid; t < 512; t += 256) {
            int r  = t & 63;
            int k4 = (t >> 6) << 2;     // 0..28
            float4 v = *(const float4*)(X + (size_t)(s0 + r) * DM + kb + k4);
            As[k4 + 0][r] = v.x; As[k4 + 1][r] = v.y;
            As[k4 + 2][r] = v.z; As[k4 + 3][r] = v.w;
        }
        // Load W tile natural: Bs[kk][c] = W[h][kb+kk][c]
        #pragma unroll
        for (int t = tid; t < 512; t += 256) {
            int kk = t >> 4;
            int c4 = (t & 15) << 2;
            *(float4*)&Bs[kk][c4] = *(const float4*)(Wh + (size_t)(kb + kk) * DHEAD + c4);
        }
        __syncthreads();

        #pragma unroll
        for (int kk = 0; kk < 32; kk++) {
            float4 a  = *(const float4*)&As[kk][ty << 2];   // uniform kk -> broadcast
            float4 bb = *(const float4*)&Bs[kk][tx << 2];   // uniform kk -> contiguous
            float av[4] = {a.x, a.y, a.z, a.w};
            float bv[4] = {bb.x, bb.y, bb.z, bb.w};
            #pragma unroll
            for (int i = 0; i < 4; i++)
                #pragma unroll
                for (int j = 0; j < 4; j++)
                    acc[i][j] += av[i] * bv[j];
        }
        __syncthreads();
    }

    float4 bias = *(const float4*)(b + h * DHEAD + (tx << 2));
    #pragma unroll
    for (int i = 0; i < 4; i++) {
        int s = s0 + (ty << 2) + i;
        float4 o;
        o.x = acc[i][0] + bias.x;
        o.y = acc[i][1] + bias.y;
        o.z = acc[i][2] + bias.z;
        o.w = acc[i][3] + bias.w;
        *(float4*)(out + ((size_t)h * SKV + s) * DHEAD + (tx << 2)) = o;
    }
}

// ---------------------------------------------------------------------------
// Fused flash attention per (head, 64-query block).
// grid = (SQ/64, NH); block = 256 (16x16 threads, 4x4 micro-tiles).
// Online softmax; writes normalized output directly into g_concat.
// smem = 3 * 16 KB = 48 KB exactly (KtP is K-tile then reused as P).
// ---------------------------------------------------------------------------
__global__ __launch_bounds__(256) void attn_kernel()
{
    __shared__ float Qt [64][64];   // Qt[d][r]
    __shared__ float KtP[64][64];   // Kt[d][j], reused as Ps[r][j]
    __shared__ float Vs [64][64];   // Vs[j][c]

    const int h   = blockIdx.y;
    const int s0  = blockIdx.x * 64;
    const int tid = threadIdx.x;
    const int ty  = tid >> 4;       // query rows ty*4..+3
    const int tx  = tid & 15;       // kv cols / out cols tx*4..+3

    const float* Qh = g_q + ((size_t)h * SQ + s0) * DHEAD;

    // Load Q tile transposed (once)
    #pragma unroll
    for (int t = tid; t < 1024; t += 256) {
        int r  = t & 63;
        int d4 = (t >> 6) << 2;
        float4 v = *(const float4*)(Qh + r * DHEAD + d4);
        Qt[d4 + 0][r] = v.x; Qt[d4 + 1][r] = v.y;
        Qt[d4 + 2][r] = v.z; Qt[d4 + 3][r] = v.w;
    }

    float m_i[4], l_i[4], O[4][4];
    #pragma unroll
    for (int i = 0; i < 4; i++) {
        m_i[i] = -3.0e38f;
        l_i[i] = 0.f;
        #pragma unroll
        for (int j = 0; j < 4; j++) O[i][j] = 0.f;
    }
    const float scale = 0.125f;   // 1/sqrt(64)

    for (int t0 = 0; t0 < SKV; t0 += 64) {
        const float* Kh = g_k + ((size_t)h * SKV + t0) * DHEAD;
        const float* Vh = g_v + ((size_t)h * SKV + t0) * DHEAD;

        __syncthreads();  // prior iter's reads of KtP/Vs done (also fences Qt on iter 0)

        // K tile transposed: KtP[d][j] = K[t0+j][d]
        #pragma unroll
        for (int t = tid; t < 1024; t += 256) {
            int j  = t & 63;
            int d4 = (t >> 6) << 2;
            float4 v = *(const float4*)(Kh + j * DHEAD + d4);
            KtP[d4 + 0][j] = v.x; KtP[d4 + 1][j] = v.y;
            KtP[d4 + 2][j] = v.z; KtP[d4 + 3][j] = v.w;
        }
        // V tile natural: Vs[j][c] = V[t0+j][c]
        #pragma unroll
        for (int t = tid; t < 1024; t += 256) {
            int j  = t >> 4;
            int c4 = (t & 15) << 2;
            *(float4*)&Vs[j][c4] = *(const float4*)(Vh + j * DHEAD + c4);
        }
        __syncthreads();

        // ---- scores s[i][j] = scale * Q[r_i] . K[j_j] ----
        float s[4][4];
        #pragma unroll
        for (int i = 0; i < 4; i++)
            #pragma unroll
            for (int j = 0; j < 4; j++) s[i][j] = 0.f;

        #pragma unroll 16
        for (int d = 0; d < 64; d++) {
            float4 a  = *(const float4*)&Qt [d][ty << 2];
            float4 bb = *(const float4*)&KtP[d][tx << 2];
            float av[4] = {a.x, a.y, a.z, a.w};
            float bv[4] = {bb.x, bb.y, bb.z, bb.w};
            #pragma unroll
            for (int i = 0; i < 4; i++)
                #pragma unroll
                for (int j = 0; j < 4; j++)
                    s[i][j] += av[i] * bv[j];
        }

        // ---- online softmax update (row state reduced across the 16 tx lanes) ----
        #pragma unroll
        for (int i = 0; i < 4; i++) {
            #pragma unroll
            for (int j = 0; j < 4; j++) s[i][j] *= scale;

            float mx = fmaxf(fmaxf(s[i][0], s[i][1]), fmaxf(s[i][2], s[i][3]));
            mx = fmaxf(mx, __shfl_xor_sync(0xffffffffu, mx, 1));
            mx = fmaxf(mx, __shfl_xor_sync(0xffffffffu, mx, 2));
            mx = fmaxf(mx, __shfl_xor_sync(0xffffffffu, mx, 4));
            mx = fmaxf(mx, __shfl_xor_sync(0xffffffffu, mx, 8));

            float m_new = fmaxf(m_i[i], mx);
            float alpha = __expf(m_i[i] - m_new);

            float rs = 0.f;
            #pragma unroll
            for (int j = 0; j < 4; j++) {
                float p = __expf(s[i][j] - m_new);
                s[i][j] = p;
                rs += p;
            }
            rs += __shfl_xor_sync(0xffffffffu, rs, 1);
            rs += __shfl_xor_sync(0xffffffffu, rs, 2);
            rs += __shfl_xor_sync(0xffffffffu, rs, 4);
            rs += __shfl_xor_sync(0xffffffffu, rs, 8);

            l_i[i] = l_i[i] * alpha + rs;
            m_i[i] = m_new;
            #pragma unroll
            for (int j = 0; j < 4; j++) O[i][j] *= alpha;
        }

        __syncthreads();  // all threads done reading KtP as K-tile

        // Write P into KtP (natural layout Ps[r][j])
        #pragma unroll
        for (int i = 0; i < 4; i++)
            *(float4*)&KtP[(ty << 2) + i][tx << 2] =
                make_float4(s[i][0], s[i][1], s[i][2], s[i][3]);
        __syncthreads();

        // ---- O[i][c] += sum_j P[r_i][j] * V[j][c] ----
        #pragma unroll 16
        for (int j = 0; j < 64; j++) {
            float4 bv = *(const float4*)&Vs[j][tx << 2];
            float a0 = KtP[(ty << 2) + 0][j];
            float a1 = KtP[(ty << 2) + 1][j];
            float a2 = KtP[(ty << 2) + 2][j];
            float a3 = KtP[(ty << 2) + 3][j];
            O[0][0] += a0 * bv.x; O[0][1] += a0 * bv.y; O[0][2] += a0 * bv.z; O[0][3] += a0 * bv.w;
            O[1][0] += a1 * bv.x; O[1][1] += a1 * bv.y; O[1][2] += a1 * bv.z; O[1][3] += a1 * bv.w;
            O[2][0] += a2 * bv.x; O[2][1] += a2 * bv.y; O[2][2] += a2 * bv.z; O[2][3] += a2 * bv.w;
            O[3][0] += a3 * bv.x; O[3][1] += a3 * bv.y; O[3][2] += a3 * bv.z; O[3][3] += a3 * bv.w;
        }
    }

    // Normalize and write into concat layout [s][h*64 + c]
    #pragma unroll
    for (int i = 0; i < 4; i++) {
        float inv = 1.0f / l_i[i];
        float4 o = make_float4(O[i][0] * inv, O[i][1] * inv, O[i][2] * inv, O[i][3] * inv);
        *(float4*)(g_concat + (size_t)(s0 + (ty << 2) + i) * DM + h * DHEAD + (tx << 2)) = o;
    }
}

// ---------------------------------------------------------------------------
// Output projection: out = concat @ Wo + bo.   Wo: [512, 512] row-major.
// grid = (SQ/64, DM/64); block = 256.
// ---------------------------------------------------------------------------
__global__ __launch_bounds__(256) void out_proj_kernel(
    const float* __restrict__ Wo,
    const float* __restrict__ bo,
    float* __restrict__ out)
{
    __shared__ float As[32][64];   // As[kk][r]
    __shared__ float Bs[32][64];   // Bs[kk][c]

    const int s0 = blockIdx.x * 64;
    const int n0 = blockIdx.y * 64;
    const int tid = threadIdx.x;
    const int ty  = tid >> 4;
    const int tx  = tid & 15;

    float acc[4][4];
    #pragma unroll
    for (int i = 0; i < 4; i++)
        #pragma unroll
        for (int j = 0; j < 4; j++) acc[i][j] = 0.f;

    for (int kb = 0; kb < DM; kb += 32) {
        #pragma unroll
        for (int t = tid; t < 512; t += 256) {
            int r  = t & 63;
            int k4 = (t >> 6) << 2;
            float4 v = *(const float4*)(g_concat + (size_t)(s0 + r) * DM + kb + k4);
            As[k4 + 0][r] = v.x; As[k4 + 1][r] = v.y;
            As[k4 + 2][r] = v.z; As[k4 + 3][r] = v.w;
        }
        #pragma unroll
        for (int t = tid; t < 512; t += 256) {
            int kk = t >> 4;
            int c4 = (t & 15) << 2;
            *(float4*)&Bs[kk][c4] = *(const float4*)(Wo + (size_t)(kb + kk) * DM + n0 + c4);
        }
        __syncthreads();

        #pragma unroll
        for (int kk = 0; kk < 32; kk++) {
            float4 a  = *(const float4*)&As[kk][ty << 2];
            float4 bb = *(const float4*)&Bs[kk][tx << 2];
            float av[4] = {a.x, a.y, a.z, a.w};
            float bv[4] = {bb.x, bb.y, bb.z, bb.w};
            #pragma unroll
            for (int i = 0; i < 4; i++)
                #pragma unroll
                for (int j = 0; j < 4; j++)
                    acc[i][j] += av[i] * bv[j];
        }
        __syncthreads();
    }

    float4 bias = *(const float4*)(bo + n0 + (tx << 2));
    #pragma unroll
    for (int i = 0; i < 4; i++) {
        int s = s0 + (ty << 2) + i;
        float4 o;
        o.x = acc[i][0] + bias.x;
        o.y = acc[i][1] + bias.y;
        o.z = acc[i][2] + bias.z;
        o.w = acc[i][3] + bias.w;
        *(float4*)(out + (size_t)s * DM + n0 + (tx << 2)) = o;
    }
}

// ---------------------------------------------------------------------------
// Launch
// ---------------------------------------------------------------------------
extern "C" void kernel_launch(void* const* d_in, const int* in_sizes, int n_in,
                              void* d_out, int out_size)
{
    const float* emb = (const float*)d_in[0];
    const float* K   = (const float*)d_in[1];
    const float* V   = (const float*)d_in[2];
    const float* Wq  = (const float*)d_in[3];
    const float* bq  = (const float*)d_in[4];
    const float* Wk  = (const float*)d_in[5];
    const float* bk  = (const float*)d_in[6];
    const float* Wv  = (const float*)d_in[7];
    const float* bv  = (const float*)d_in[8];
    const float* Wo  = (const float*)d_in[9];
    const float* bo  = (const float*)d_in[10];
    float* out = (float*)d_out;

    dim3 blk(256);

    // Q/K/V projections in one launch (z selects which projection)
    proj_qkv_kernel<<<dim3(SQ / 64, NH, 3), blk>>>(
        emb, Wq, bq,
        K,   Wk, bk,
        V,   Wv, bv);

    // Fused flash attention -> g_concat
    attn_kernel<<<dim3(SQ / 64, NH), blk>>>();

    // Final output projection
    out_proj_kernel<<<dim3(SQ / 64, DM / 64), blk>>>(Wo, bo, out);
}

// round 10
// speedup vs baseline: 1.0730x; 1.0723x over previous
#include <cuda_runtime.h>
#include <math.h>

#define SQ    2048
#define SKV   2048
#define DM    512
#define NH    8
#define DHEAD 64

// ---------------------------------------------------------------------------
// Scratch (device globals: allocation-guard safe)
// ---------------------------------------------------------------------------
__device__ float g_q[NH * SQ * DHEAD];        // [h][s][d]
__device__ float g_k[NH * SKV * DHEAD];       // [h][t][d]
__device__ float g_v[NH * SKV * DHEAD];       // [h][t][d]
__device__ float g_concat[SQ * DM];           // [s][h*64 + c]

// ---------------------------------------------------------------------------
// Q/K/V projection GEMMs.  grid=(SQ/128, NH, 3); block=128.
// BM=128, BN=64, BK=32; 8x8 micro-tile (ty=tid>>3 rows, tx=tid&7 cols).
// ---------------------------------------------------------------------------
__global__ __launch_bounds__(128, 4) void proj_qkv_kernel(
    const float* __restrict__ X0, const float* __restrict__ W0, const float* __restrict__ b0,
    const float* __restrict__ X1, const float* __restrict__ W1, const float* __restrict__ b1,
    const float* __restrict__ X2, const float* __restrict__ W2, const float* __restrict__ b2)
{
    __shared__ float As[32][128];   // As[kk][r]  (X tile, transposed)
    __shared__ float Bs[32][64];    // Bs[kk][c]  (W tile, natural)

    const float* X; const float* W; const float* b; float* out;
    if (blockIdx.z == 0)      { X = X0; W = W0; b = b0; out = g_q; }
    else if (blockIdx.z == 1) { X = X1; W = W1; b = b1; out = g_k; }
    else                      { X = X2; W = W2; b = b2; out = g_v; }

    const int h  = blockIdx.y;
    const int s0 = blockIdx.x * 128;
    const float* Wh = W + (size_t)h * DM * DHEAD;

    const int tid = threadIdx.x;
    const int ty8 = (tid >> 3) << 3;   // row base 0..120
    const int tx8 = (tid & 7) << 3;    // col base 0..56

    float acc[8][8];
    #pragma unroll
    for (int i = 0; i < 8; i++)
        #pragma unroll
        for (int j = 0; j < 8; j++) acc[i][j] = 0.f;

    const float* Xrow = X + (size_t)(s0 + tid) * DM;

    for (int kb = 0; kb < DM; kb += 32) {
        // A tile transposed: thread owns row r=tid; reads 32 contiguous k.
        #pragma unroll
        for (int i = 0; i < 8; i++) {
            float4 v = *(const float4*)(Xrow + kb + i * 4);
            As[i * 4 + 0][tid] = v.x; As[i * 4 + 1][tid] = v.y;
            As[i * 4 + 2][tid] = v.z; As[i * 4 + 3][tid] = v.w;
        }
        // B tile natural
        #pragma unroll
        for (int i = 0; i < 4; i++) {
            int t  = tid + i * 128;
            int kk = t >> 4;
            int c4 = (t & 15) << 2;
            *(float4*)&Bs[kk][c4] = *(const float4*)(Wh + (size_t)(kb + kk) * DHEAD + c4);
        }
        __syncthreads();

        #pragma unroll 8
        for (int kk = 0; kk < 32; kk++) {
            float4 a0 = *(const float4*)&As[kk][ty8];
            float4 a1 = *(const float4*)&As[kk][ty8 + 4];
            float4 c0 = *(const float4*)&Bs[kk][tx8];
            float4 c1 = *(const float4*)&Bs[kk][tx8 + 4];
            float av[8] = {a0.x, a0.y, a0.z, a0.w, a1.x, a1.y, a1.z, a1.w};
            float bv[8] = {c0.x, c0.y, c0.z, c0.w, c1.x, c1.y, c1.z, c1.w};
            #pragma unroll
            for (int i = 0; i < 8; i++)
                #pragma unroll
                for (int j = 0; j < 8; j++)
                    acc[i][j] += av[i] * bv[j];
        }
        __syncthreads();
    }

    float4 bi0 = *(const float4*)(b + h * DHEAD + tx8);
    float4 bi1 = *(const float4*)(b + h * DHEAD + tx8 + 4);
    float bias[8] = {bi0.x, bi0.y, bi0.z, bi0.w, bi1.x, bi1.y, bi1.z, bi1.w};
    #pragma unroll
    for (int i = 0; i < 8; i++) {
        float* orow = out + ((size_t)h * SQ + s0 + ty8 + i) * DHEAD + tx8;
        float4 o0 = make_float4(acc[i][0] + bias[0], acc[i][1] + bias[1],
                                acc[i][2] + bias[2], acc[i][3] + bias[3]);
        float4 o1 = make_float4(acc[i][4] + bias[4], acc[i][5] + bias[5],
                                acc[i][6] + bias[6], acc[i][7] + bias[7]);
        *(float4*)orow = o0;
        *(float4*)(orow + 4) = o1;
    }
}

// ---------------------------------------------------------------------------
// Fused flash attention.  grid=(SQ/64, NH); block=128.
// BQ=64, BKV=64; ty=tid>>4 (rows ty*8), tx=tid&15 (cols tx*4).
// 8x4 micro-tiles on both GEMMs. smem 48 KB (KtPs = K tile then P tile).
// ---------------------------------------------------------------------------
__global__ __launch_bounds__(128, 4) void attn_kernel()
{
    __shared__ float Qt  [64][64];   // Qt[d][r]
    __shared__ float KtPs[64][64];   // Kt[d][j], reused as Ps[r][j]
    __shared__ float Vs  [64][64];   // Vs[j][c]

    const int h   = blockIdx.y;
    const int s0  = blockIdx.x * 64;
    const int tid = threadIdx.x;
    const int ty8 = (tid >> 4) << 3;   // query row base 0..56
    const int tx4 = (tid & 15) << 2;   // col base 0..60

    const float* Qh = g_q + ((size_t)h * SQ + s0) * DHEAD;

    // Load Q tile transposed (once)
    #pragma unroll
    for (int i = 0; i < 8; i++) {
        int t  = tid + i * 128;
        int r  = t & 63;
        int d4 = (t >> 6) << 2;
        float4 v = *(const float4*)(Qh + r * DHEAD + d4);
        Qt[d4 + 0][r] = v.x; Qt[d4 + 1][r] = v.y;
        Qt[d4 + 2][r] = v.z; Qt[d4 + 3][r] = v.w;
    }

    float m_i[8], l_i[8], O[8][4];
    #pragma unroll
    for (int i = 0; i < 8; i++) {
        m_i[i] = -3.0e38f;
        l_i[i] = 0.f;
        #pragma unroll
        for (int j = 0; j < 4; j++) O[i][j] = 0.f;
    }
    const float scale = 0.125f;   // 1/sqrt(64)

    for (int t0 = 0; t0 < SKV; t0 += 64) {
        const float* Kh = g_k + ((size_t)h * SKV + t0) * DHEAD;
        const float* Vh = g_v + ((size_t)h * SKV + t0) * DHEAD;

        __syncthreads();  // prior iter reads of KtPs/Vs done (fences Qt on iter 0)

        // K tile transposed: KtPs[d][j] = K[t0+j][d]
        #pragma unroll
        for (int i = 0; i < 8; i++) {
            int t  = tid + i * 128;
            int j  = t & 63;
            int d4 = (t >> 6) << 2;
            float4 v = *(const float4*)(Kh + j * DHEAD + d4);
            KtPs[d4 + 0][j] = v.x; KtPs[d4 + 1][j] = v.y;
            KtPs[d4 + 2][j] = v.z; KtPs[d4 + 3][j] = v.w;
        }
        // V tile natural
        #pragma unroll
        for (int i = 0; i < 8; i++) {
            int t  = tid + i * 128;
            int j  = t >> 4;
            int c4 = (t & 15) << 2;
            *(float4*)&Vs[j][c4] = *(const float4*)(Vh + j * DHEAD + c4);
        }
        __syncthreads();

        // ---- scores p[i][j] = Q[ty8+i] . K[tx4+j] ----
        float p[8][4];
        #pragma unroll
        for (int i = 0; i < 8; i++)
            #pragma unroll
            for (int j = 0; j < 4; j++) p[i][j] = 0.f;

        #pragma unroll 8
        for (int d = 0; d < 64; d++) {
            float4 a0 = *(const float4*)&Qt[d][ty8];
            float4 a1 = *(const float4*)&Qt[d][ty8 + 4];
            float4 bb = *(const float4*)&KtPs[d][tx4];
            float av[8] = {a0.x, a0.y, a0.z, a0.w, a1.x, a1.y, a1.z, a1.w};
            float bv[4] = {bb.x, bb.y, bb.z, bb.w};
            #pragma unroll
            for (int i = 0; i < 8; i++)
                #pragma unroll
                for (int j = 0; j < 4; j++)
                    p[i][j] += av[i] * bv[j];
        }

        // ---- online softmax (row state reduced across the 16 tx lanes) ----
        #pragma unroll
        for (int i = 0; i < 8; i++) {
            #pragma unroll
            for (int j = 0; j < 4; j++) p[i][j] *= scale;

            float mx = fmaxf(fmaxf(p[i][0], p[i][1]), fmaxf(p[i][2], p[i][3]));
            mx = fmaxf(mx, __shfl_xor_sync(0xffffffffu, mx, 1));
            mx = fmaxf(mx, __shfl_xor_sync(0xffffffffu, mx, 2));
            mx = fmaxf(mx, __shfl_xor_sync(0xffffffffu, mx, 4));
            mx = fmaxf(mx, __shfl_xor_sync(0xffffffffu, mx, 8));

            float m_new = fmaxf(m_i[i], mx);
            float alpha = __expf(m_i[i] - m_new);

            float rs = 0.f;
            #pragma unroll
            for (int j = 0; j < 4; j++) {
                float e = __expf(p[i][j] - m_new);
                p[i][j] = e;
                rs += e;
            }
            rs += __shfl_xor_sync(0xffffffffu, rs, 1);
            rs += __shfl_xor_sync(0xffffffffu, rs, 2);
            rs += __shfl_xor_sync(0xffffffffu, rs, 4);
            rs += __shfl_xor_sync(0xffffffffu, rs, 8);

            l_i[i] = l_i[i] * alpha + rs;
            m_i[i] = m_new;
            #pragma unroll
            for (int j = 0; j < 4; j++) O[i][j] *= alpha;
        }

        __syncthreads();  // all S-reads of KtPs done

        // Write P: Ps[r][j] (natural)
        #pragma unroll
        for (int i = 0; i < 8; i++)
            *(float4*)&KtPs[ty8 + i][tx4] = make_float4(p[i][0], p[i][1], p[i][2], p[i][3]);
        __syncthreads();

        // ---- O[i][c] += sum_j P[ty8+i][j] * V[j][c] ----
        #pragma unroll 4
        for (int jf = 0; jf < 16; jf++) {
            float4 b0 = *(const float4*)&Vs[jf * 4 + 0][tx4];
            float4 b1 = *(const float4*)&Vs[jf * 4 + 1][tx4];
            float4 b2 = *(const float4*)&Vs[jf * 4 + 2][tx4];
            float4 b3 = *(const float4*)&Vs[jf * 4 + 3][tx4];
            #pragma unroll
            for (int i = 0; i < 8; i++) {
                float4 a = *(const float4*)&KtPs[ty8 + i][jf * 4];
                O[i][0] += a.x * b0.x + a.y * b1.x + a.z * b2.x + a.w * b3.x;
                O[i][1] += a.x * b0.y + a.y * b1.y + a.z * b2.y + a.w * b3.y;
                O[i][2] += a.x * b0.z + a.y * b1.z + a.z * b2.z + a.w * b3.z;
                O[i][3] += a.x * b0.w + a.y * b1.w + a.z * b2.w + a.w * b3.w;
            }
        }
    }

    // Normalize and write into concat layout [s][h*64 + c]
    #pragma unroll
    for (int i = 0; i < 8; i++) {
        float inv = 1.0f / l_i[i];
        float4 o = make_float4(O[i][0] * inv, O[i][1] * inv, O[i][2] * inv, O[i][3] * inv);
        *(float4*)(g_concat + (size_t)(s0 + ty8 + i) * DM + h * DHEAD + tx4) = o;
    }
}

// ---------------------------------------------------------------------------
// Output projection: out = concat @ Wo + bo.  Wo: [512,512] row-major.
// grid=(SQ/128, DM/64); block=128.  Same 8x8 structure as proj.
// ---------------------------------------------------------------------------
__global__ __launch_bounds__(128, 4) void out_proj_kernel(
    const float* __restrict__ Wo,
    const float* __restrict__ bo,
    float* __restrict__ out)
{
    __shared__ float As[32][128];
    __shared__ float Bs[32][64];

    const int s0 = blockIdx.x * 128;
    const int n0 = blockIdx.y * 64;
    const int tid = threadIdx.x;
    const int ty8 = (tid >> 3) << 3;
    const int tx8 = (tid & 7) << 3;

    float acc[8][8];
    #pragma unroll
    for (int i = 0; i < 8; i++)
        #pragma unroll
        for (int j = 0; j < 8; j++) acc[i][j] = 0.f;

    const float* Xrow = g_concat + (size_t)(s0 + tid) * DM;

    for (int kb = 0; kb < DM; kb += 32) {
        #pragma unroll
        for (int i = 0; i < 8; i++) {
            float4 v = *(const float4*)(Xrow + kb + i * 4);
            As[i * 4 + 0][tid] = v.x; As[i * 4 + 1][tid] = v.y;
            As[i * 4 + 2][tid] = v.z; As[i * 4 + 3][tid] = v.w;
        }
        #pragma unroll
        for (int i = 0; i < 4; i++) {
            int t  = tid + i * 128;
            int kk = t >> 4;
            int c4 = (t & 15) << 2;
            *(float4*)&Bs[kk][c4] = *(const float4*)(Wo + (size_t)(kb + kk) * DM + n0 + c4);
        }
        __syncthreads();

        #pragma unroll 8
        for (int kk = 0; kk < 32; kk++) {
            float4 a0 = *(const float4*)&As[kk][ty8];
            float4 a1 = *(const float4*)&As[kk][ty8 + 4];
            float4 c0 = *(const float4*)&Bs[kk][tx8];
            float4 c1 = *(const float4*)&Bs[kk][tx8 + 4];
            float av[8] = {a0.x, a0.y, a0.z, a0.w, a1.x, a1.y, a1.z, a1.w};
            float bv[8] = {c0.x, c0.y, c0.z, c0.w, c1.x, c1.y, c1.z, c1.w};
            #pragma unroll
            for (int i = 0; i < 8; i++)
                #pragma unroll
                for (int j = 0; j < 8; j++)
                    acc[i][j] += av[i] * bv[j];
        }
        __syncthreads();
    }

    float4 bi0 = *(const float4*)(bo + n0 + tx8);
    float4 bi1 = *(const float4*)(bo + n0 + tx8 + 4);
    float bias[8] = {bi0.x, bi0.y, bi0.z, bi0.w, bi1.x, bi1.y, bi1.z, bi1.w};
    #pragma unroll
    for (int i = 0; i < 8; i++) {
        float* orow = out + (size_t)(s0 + ty8 + i) * DM + n0 + tx8;
        float4 o0 = make_float4(acc[i][0] + bias[0], acc[i][1] + bias[1],
                                acc[i][2] + bias[2], acc[i][3] + bias[3]);
        float4 o1 = make_float4(acc[i][4] + bias[4], acc[i][5] + bias[5],
                                acc[i][6] + bias[6], acc[i][7] + bias[7]);
        *(float4*)orow = o0;
        *(float4*)(orow + 4) = o1;
    }
}

// ---------------------------------------------------------------------------
// Launch
// ---------------------------------------------------------------------------
extern "C" void kernel_launch(void* const* d_in, const int* in_sizes, int n_in,
                              void* d_out, int out_size)
{
    const float* emb = (const float*)d_in[0];
    const float* K   = (const float*)d_in[1];
    const float* V   = (const float*)d_in[2];
    const float* Wq  = (const float*)d_in[3];
    const float* bq  = (const float*)d_in[4];
    const float* Wk  = (const float*)d_in[5];
    const float* bk  = (const float*)d_in[6];
    const float* Wv  = (const float*)d_in[7];
    const float* bv  = (const float*)d_in[8];
    const float* Wo  = (const float*)d_in[9];
    const float* bo  = (const float*)d_in[10];
    float* out = (float*)d_out;

    dim3 blk(128);

    proj_qkv_kernel<<<dim3(SQ / 128, NH, 3), blk>>>(
        emb, Wq, bq,
        K,   Wk, bk,
        V,   Wv, bv);

    attn_kernel<<<dim3(SQ / 64, NH), blk>>>();

    out_proj_kernel<<<dim3(SQ / 128, DM / 64), blk>>>(Wo, bo, out);
}